// round 5
// baseline (speedup 1.0000x reference)
#include <cuda_runtime.h>
#include <cstdint>

// Problem constants
#define ROWS_TOTAL 16384      // 4 * 4096 (batch * seq)
#define DIMK 4096             // inner dim
#define RR 8                  // LoRA rank
#define NL 3                  // number of LoRAs
#define LRTOT 24              // NL * RR
#define OUT_DIM 12288         // NL * 4096
#define LORA_OUT 4096

#define NXA (ROWS_TOTAL * LRTOT)   // 393216
#define KS  4                      // split-K slices
#define DKC 16                     // d per chunk (2 buf stages)
#define BROWS 256                  // rows per xa block
#define XROWP 260                  // padded row stride (float4 units)

typedef unsigned long long ull;

// -------- scratch (no allocations allowed) --------
__device__ float2 g_Apk2[(DIMK / 2) * LRTOT];  // A packed as d-pairs: [d2][lr]
__device__ float  g_xap[KS * NXA];             // XA partials per k-slice

__device__ __forceinline__ void ffma2(ull& acc, ull a, ull b) {
    asm("fma.rn.f32x2 %0, %1, %2, %0;" : "+l"(acc) : "l"(a), "l"(b));
}

__device__ __forceinline__ void cp_async16(void* smem_dst, const void* gptr) {
    unsigned s = (unsigned)__cvta_generic_to_shared(smem_dst);
    asm volatile("cp.async.cg.shared.global [%0], [%1], 16;\n" :: "r"(s), "l"(gptr));
}
__device__ __forceinline__ void cp_commit() {
    asm volatile("cp.async.commit_group;\n" ::: "memory");
}
__device__ __forceinline__ void cp_wait1() {
    asm volatile("cp.async.wait_group 1;\n" ::: "memory");
}
__device__ __forceinline__ void cp_wait0() {
    asm volatile("cp.async.wait_group 0;\n" ::: "memory");
}

// ============================================================
// k0: pack A0/A1/A2 ([dim][r] row-major) -> g_Apk2 [d2][lr] float2
//     g_Apk2[d2*24+lr] = (A[2*d2][r], A[2*d2+1][r])
// ============================================================
__global__ void pack_A_kernel(const float* __restrict__ A0,
                              const float* __restrict__ A1,
                              const float* __restrict__ A2) {
    int idx = blockIdx.x * blockDim.x + threadIdx.x;   // over (DIMK/2)*LRTOT
    if (idx >= (DIMK / 2) * LRTOT) return;
    int d2 = idx / LRTOT;
    int lr = idx % LRTOT;
    int l  = lr >> 3;
    int r  = lr & 7;
    const float* A = (l == 0) ? A0 : (l == 1) ? A1 : A2;
    g_Apk2[idx] = make_float2(A[(2 * d2) * RR + r], A[(2 * d2 + 1) * RR + r]);
}

// ============================================================
// k1: XA = x @ Acat, split-K x4, cp.async double-buffered.
// Block: 256 threads, 256 rows. Thread tile: 4 rows x 6 lr.
//   rg = tid & 63  -> rows rg + 64*i (i=0..3)
//   lg = tid >> 6  -> lrs  lg*6 + j  (j=0..5)
// x staged d-packed: xs[buf][d4][row] = float4 of 4 consecutive d
//   (read as LDS.128, reused across 2 d-pairs).
// A staged as d-pairs: as2[buf][dp][lr].
// f32x2 accumulator halves = even-d / odd-d partial sums.
// ============================================================
__global__ __launch_bounds__(256, 2) void xa_kernel(const float* __restrict__ x) {
    __shared__ float4 xs[2][DKC / 4][XROWP];       // 2*4*260*16 = 33.3 KB
    __shared__ float2 as2[2][DKC / 2][LRTOT];      // 2*8*24*8   =  3 KB

    int tid = threadIdx.x;
    int rg  = tid & 63;
    int lg  = tid >> 6;
    int rowBase = blockIdx.x * BROWS;
    int dBase   = blockIdx.y * (DIMK / KS);
    const int NC = (DIMK / KS) / DKC;              // 64 chunks

    // per-thread staging coords (x): 4 ops, e = it*256+tid, row=e>>2, d4=e&3
    // per-thread staging coords (A): first 96 threads, 16B = 2 lr of one dp
    int a_d2  = tid / 12;        // 0..7  (valid when tid < 96)
    int a_lrp = tid % 12;        // 0..11 -> lr = 2*a_lrp

    ull acc[4][6];
#pragma unroll
    for (int i = 0; i < 4; i++)
#pragma unroll
        for (int j = 0; j < 6; j++) acc[i][j] = 0ull;

    // ---- stage chunk 0 ----
    {
        int dc = dBase;
#pragma unroll
        for (int it = 0; it < 4; it++) {
            int e   = it * 256 + tid;
            int row = e >> 2;
            int d4  = e & 3;
            cp_async16(&xs[0][d4][row],
                       x + (size_t)(rowBase + row) * DIMK + dc + 4 * d4);
        }
        if (tid < 96) {
            cp_async16(&as2[0][a_d2][2 * a_lrp],
                       g_Apk2 + (size_t)(dc / 2 + a_d2) * LRTOT + 2 * a_lrp);
        }
        cp_commit();
    }

    for (int c = 0; c < NC; c++) {
        int b = c & 1;
        // ---- prefetch chunk c+1 into alt buffer ----
        if (c + 1 < NC) {
            int dc = dBase + (c + 1) * DKC;
#pragma unroll
            for (int it = 0; it < 4; it++) {
                int e   = it * 256 + tid;
                int row = e >> 2;
                int d4  = e & 3;
                cp_async16(&xs[b ^ 1][d4][row],
                           x + (size_t)(rowBase + row) * DIMK + dc + 4 * d4);
            }
            if (tid < 96) {
                cp_async16(&as2[b ^ 1][a_d2][2 * a_lrp],
                           g_Apk2 + (size_t)(dc / 2 + a_d2) * LRTOT + 2 * a_lrp);
            }
            cp_commit();
            cp_wait1();          // chunk c complete, c+1 in flight
        } else {
            cp_wait0();
        }
        __syncthreads();

        // ---- compute chunk c: 4 d4-iterations, 2 d-pairs each ----
#pragma unroll
        for (int d4 = 0; d4 < DKC / 4; d4++) {
            // x: 4 rows, full float4 (both d-pairs), conflict-free LDS.128
            float4 xq[4];
#pragma unroll
            for (int i = 0; i < 4; i++)
                xq[i] = xs[b][d4][rg + 64 * i];

#pragma unroll
            for (int half = 0; half < 2; half++) {
                int dp = 2 * d4 + half;
                ull ap[6];
#pragma unroll
                for (int q = 0; q < 3; q++) {
                    ulonglong2 t = *reinterpret_cast<const ulonglong2*>(
                        &as2[b][dp][lg * 6 + 2 * q]);
                    ap[2 * q]     = t.x;
                    ap[2 * q + 1] = t.y;
                }
                ull xp[4];
#pragma unroll
                for (int i = 0; i < 4; i++) {
                    const float* f = reinterpret_cast<const float*>(&xq[i]);
                    float2 p = make_float2(f[2 * half], f[2 * half + 1]);
                    xp[i] = *reinterpret_cast<const ull*>(&p);
                }
#pragma unroll
                for (int i = 0; i < 4; i++)
#pragma unroll
                    for (int j = 0; j < 6; j++)
                        ffma2(acc[i][j], xp[i], ap[j]);
            }
        }
        __syncthreads();   // protect buf b before chunk c+2 overwrites it
    }

    // write partials: sum even/odd halves
#pragma unroll
    for (int i = 0; i < 4; i++)
#pragma unroll
        for (int j = 0; j < 6; j++) {
            float2 v = *reinterpret_cast<float2*>(&acc[i][j]);
            int row = rowBase + rg + 64 * i;
            g_xap[(size_t)blockIdx.y * NXA + (size_t)row * LRTOT + lg * 6 + j] =
                v.x + v.y;
        }
}

// ============================================================
// k2: out = XA @ B (per lora), f32x2; folds the split-K reduce.
// Grid: (4 col tiles, 512 row tiles, 3 loras). Block: 256 thr.
// Each block: 32 rows x 1024 cols of one lora.
// ============================================================
#define R2ROWS 32

__global__ __launch_bounds__(256, 4) void out_kernel(const float* __restrict__ B0,
                                                     const float* __restrict__ B1,
                                                     const float* __restrict__ B2,
                                                     float* __restrict__ out) {
    int l = blockIdx.z;
    const float* B = (l == 0) ? B0 : (l == 1) ? B1 : B2;
    int rowBase = blockIdx.y * R2ROWS;
    int o = blockIdx.x * 1024 + threadIdx.x * 4;   // column within this lora

    __shared__ float2 xa_s[R2ROWS][RR];            // duplicated (s,s)
    {
        int i = threadIdx.x >> 3;
        int r = threadIdx.x & 7;
        size_t base = (size_t)(rowBase + i) * LRTOT + l * RR + r;
        float s = g_xap[base] + g_xap[NXA + base] +
                  g_xap[2 * (size_t)NXA + base] + g_xap[3 * (size_t)NXA + base];
        xa_s[i][r] = make_float2(s, s);
    }
    __syncthreads();

    // B columns o..o+3 for all 8 r, as f32x2 pairs
    ull blo[RR], bhi[RR];
#pragma unroll
    for (int r = 0; r < RR; r++) {
        float4 b = *reinterpret_cast<const float4*>(B + r * LORA_OUT + o);
        ulonglong2 u = *reinterpret_cast<ulonglong2*>(&b);
        blo[r] = u.x;
        bhi[r] = u.y;
    }

#pragma unroll 4
    for (int i = 0; i < R2ROWS; i++) {
        ull s[RR];
#pragma unroll
        for (int r = 0; r < RR; r++)
            s[r] = *reinterpret_cast<const ull*>(&xa_s[i][r]);   // broadcast

        ull a0 = 0ull, a1 = 0ull;
#pragma unroll
        for (int r = 0; r < RR; r++) {
            ffma2(a0, s[r], blo[r]);
            ffma2(a1, s[r], bhi[r]);
        }
        float4 res;
        *reinterpret_cast<ull*>(&res.x) = a0;
        *reinterpret_cast<ull*>(&res.z) = a1;

        size_t oidx = (size_t)(rowBase + i) * OUT_DIM + (size_t)l * LORA_OUT + o;
        __stcs(reinterpret_cast<float4*>(out + oidx), res);
    }
}

// ============================================================
// launch
// ============================================================
extern "C" void kernel_launch(void* const* d_in, const int* in_sizes, int n_in,
                              void* d_out, int out_size) {
    const float* x  = (const float*)d_in[0];
    const float* A0 = (const float*)d_in[1];
    const float* B0 = (const float*)d_in[2];
    const float* A1 = (const float*)d_in[3];
    const float* B1 = (const float*)d_in[4];
    const float* A2 = (const float*)d_in[5];
    const float* B2 = (const float*)d_in[6];
    float* out = (float*)d_out;

    pack_A_kernel<<<((DIMK / 2) * LRTOT + 255) / 256, 256>>>(A0, A1, A2);

    dim3 grid1(ROWS_TOTAL / BROWS, KS);            // 64 x 4 = 256 blocks
    xa_kernel<<<grid1, 256>>>(x);

    dim3 grid2(LORA_OUT / 1024, ROWS_TOTAL / R2ROWS, NL);  // 4 x 512 x 3
    out_kernel<<<grid2, 256>>>(B0, B1, B2, out);
}